// round 3
// baseline (speedup 1.0000x reference)
#include <cuda_runtime.h>
#include <cstdint>

#define TT 512
#define BB 64
#define HH 512

typedef unsigned long long ull;

// ---------------- device scratch (static: no runtime allocation) ----------------
__device__ float g_xT[(size_t)TT * HH * BB];   // [t][k][b]  (64 MB)
__device__ float g_h[2][HH * BB];              // double-buffered h, [buf][k*B + b]
__device__ unsigned g_bar;                     // grid barrier counter
__device__ int g_r_u8;                         // 1 if resets is 1-byte bool, 0 if int32

// ---------------- helpers ----------------
static __device__ __forceinline__ ull ffma2(ull a, ull b, ull c) {
    ull d;
    asm("fma.rn.f32x2 %0, %1, %2, %3;" : "=l"(d) : "l"(a), "l"(b), "l"(c));
    return d;
}
static __device__ __forceinline__ float lo32(ull v) { return __uint_as_float((unsigned)(v & 0xffffffffull)); }
static __device__ __forceinline__ float hi32(ull v) { return __uint_as_float((unsigned)(v >> 32)); }
static __device__ __forceinline__ float sigf(float x) { return 1.0f / (1.0f + __expf(-x)); }
static __device__ __forceinline__ float clampf1(float x) { return fminf(fmaxf(x, -1.0f), 1.0f); }

// ---------------- kernel 0: reset-dtype detection + barrier reset ----------------
__global__ void k_detect(const unsigned char* __restrict__ r) {
    __shared__ int nz;
    if (threadIdx.x == 0) { nz = 0; g_bar = 0u; }
    __syncthreads();
    int loc = 0;
    // Scan first T*B bytes (valid for both u8[T*B] and i32[T*B] buffers).
    // If dtype is int32 with values 0/1, every byte at offset i%4!=0 is zero.
    for (int i = threadIdx.x; i < TT * BB; i += blockDim.x)
        if ((i & 3) && r[i]) loc = 1;
    if (loc) atomicOr(&nz, 1);
    __syncthreads();
    if (threadIdx.x == 0) g_r_u8 = nz;
}

// ---------------- kernel 1: transpose xs -> xT[t][k][b]; init h buffer ----------------
__global__ void k_prep(const float* __restrict__ xs, const float* __restrict__ h0,
                       const void* __restrict__ resets) {
    __shared__ float tile[64][65];
    const int t = blockIdx.x;
    for (int kt = 0; kt < 8; ++kt) {
        for (int idx = threadIdx.x; idx < 64 * 64; idx += blockDim.x) {
            int bb = idx >> 6, kk = idx & 63;
            tile[bb][kk] = xs[((size_t)t * BB + bb) * HH + kt * 64 + kk];
        }
        __syncthreads();
        for (int idx = threadIdx.x; idx < 64 * 64; idx += blockDim.x) {
            int kk = idx >> 6, bb = idx & 63;
            g_xT[(size_t)t * HH * BB + (size_t)(kt * 64 + kk) * BB + bb] = tile[bb][kk];
        }
        __syncthreads();
    }
    if (t == 0) {
        const int ru8 = g_r_u8;
        const unsigned char* r8 = (const unsigned char*)resets;
        const int* r32 = (const int*)resets;
        for (int idx = threadIdx.x; idx < HH * BB; idx += blockDim.x) {
            int b = idx & 63, k = idx >> 6;
            bool rs = ru8 ? (r8[b] != 0) : (r32[b] != 0);   // resets[0][b]
            g_h[0][idx] = rs ? 0.0f : h0[b * HH + k];
        }
    }
}

// ---------------- kernel 2: persistent scanned-LSTM ----------------
// 128 CTAs x 256 threads. CTA c owns state columns j in [4c, 4c+4).
// SMEM: weights duplicated as f32 pairs: wdup[k][m][l] (m: 0=Wi,1=Wh; l = gate*4 + j), 128KB
//       + z buffer [2 split-k halves][64 b][16 local zcols], 8KB.
#define SMEM_BYTES (131072 + 8192)

#define LOADBLK(XR, HR, blk) do {                                              \
    _Pragma("unroll")                                                          \
    for (int u = 0; u < 4; ++u) {                                              \
        double2 xv = __ldcg((const double2*)(xTt + ((blk) * 4 + u) * BB));     \
        double2 hv = __ldcg((const double2*)(hbp + ((blk) * 4 + u) * BB));     \
        XR[2 * u]     = __double_as_longlong(xv.x);                            \
        XR[2 * u + 1] = __double_as_longlong(xv.y);                            \
        HR[2 * u]     = __double_as_longlong(hv.x);                            \
        HR[2 * u + 1] = __double_as_longlong(hv.y);                            \
    } } while (0)

#define COMPUTE(XR, HR, blkbase) do {                                          \
    _Pragma("unroll")                                                          \
    for (int u = 0; u < 4; ++u) {                                              \
        const ulonglong2 wiv = wp[((blkbase) * 4 + u) * 16];                   \
        const ulonglong2 whv = wp[((blkbase) * 4 + u) * 16 + 8];               \
        a00 = ffma2(wiv.x, XR[2 * u],     a00);                                \
        a00 = ffma2(whv.x, HR[2 * u],     a00);                                \
        a01 = ffma2(wiv.x, XR[2 * u + 1], a01);                                \
        a01 = ffma2(whv.x, HR[2 * u + 1], a01);                                \
        a10 = ffma2(wiv.y, XR[2 * u],     a10);                                \
        a10 = ffma2(whv.y, HR[2 * u],     a10);                                \
        a11 = ffma2(wiv.y, XR[2 * u + 1], a11);                                \
        a11 = ffma2(whv.y, HR[2 * u + 1], a11);                                \
    } } while (0)

__global__ __launch_bounds__(256, 1)
void lstm_main(const float* __restrict__ Wi, const float* __restrict__ Wh,
               const float* __restrict__ bias, const float* __restrict__ c0,
               const void* __restrict__ resets, float* __restrict__ ys) {
    extern __shared__ char smem[];
    float2* wdup = (float2*)smem;                    // 512 k * 32 entries (dup pairs)
    float*  zbuf = (float*)(smem + 131072);          // [2][64][16]

    const int tid = threadIdx.x;
    const int cta = blockIdx.x;

    // ---- prologue: load this CTA's weight slice, duplicated into pairs ----
    for (int idx = tid; idx < 512 * 32; idx += 256) {
        int k = idx >> 5, r = idx & 31, m = r >> 4, l = r & 15;
        int g = l >> 2, j = l & 3;
        int col = g * 512 + cta * 4 + j;
        float w = (m ? Wh : Wi)[k * 2048 + col];
        wdup[idx] = make_float2(w, w);
    }

    // ---- per-thread epilogue identity: one (b, j) state element ----
    const int eb = tid >> 2;           // 0..63
    const int ej = tid & 3;            // 0..3
    const int jcol = cta * 4 + ej;     // global H index
    float c = c0[eb * HH + jcol];
    const float bi = bias[jcol];
    const float bf = bias[512 + jcol];
    const float bg = bias[1024 + jcol];
    const float bo = bias[1536 + jcol];
    const int ru8 = g_r_u8;
    const unsigned char* r8 = (const unsigned char*)resets;
    const int* r32 = (const int*)resets;

    // ---- GEMM identity: split-k halves, col-pair p, b-quad ----
    const int khalf = tid >> 7;        // 0 or 1 (k in [0,256) or [256,512))
    const int tl = tid & 127;
    const int p = tl & 7;              // col pair (local zcols 2p, 2p+1)
    const int bq = tl >> 3;            // 0..15
    const int b0 = bq * 4;
    const int kbeg = khalf * 256;
    const ulonglong2* wp = (const ulonglong2*)(wdup + kbeg * 32 + 2 * p); // per-k stride: 16 ulonglong2
    float* zb = zbuf + khalf * 1024;

    __syncthreads();

    const unsigned nblocks = gridDim.x;

    for (int t = 0; t < TT; ++t) {
        const float* xTt = g_xT + (size_t)t * (HH * BB) + kbeg * BB + b0;
        const float* hbp = g_h[t & 1] + kbeg * BB + b0;

        ull a00 = 0, a01 = 0, a10 = 0, a11 = 0;
        ull xrA[8], hrA[8], xrB[8], hrB[8];
        LOADBLK(xrA, hrA, 0);
        LOADBLK(xrB, hrB, 1);
        #pragma unroll 1
        for (int blk = 0; blk < 64; blk += 2) {
            COMPUTE(xrA, hrA, blk);
            if (blk + 2 < 64) LOADBLK(xrA, hrA, blk + 2);
            COMPUTE(xrB, hrB, blk + 1);
            if (blk + 3 < 64) LOADBLK(xrB, hrB, blk + 3);
        }

        // write z partials to SMEM
        zb[(b0 + 0) * 16 + 2 * p]     = lo32(a00);
        zb[(b0 + 1) * 16 + 2 * p]     = hi32(a00);
        zb[(b0 + 2) * 16 + 2 * p]     = lo32(a01);
        zb[(b0 + 3) * 16 + 2 * p]     = hi32(a01);
        zb[(b0 + 0) * 16 + 2 * p + 1] = lo32(a10);
        zb[(b0 + 1) * 16 + 2 * p + 1] = hi32(a10);
        zb[(b0 + 2) * 16 + 2 * p + 1] = lo32(a11);
        zb[(b0 + 3) * 16 + 2 * p + 1] = hi32(a11);
        __syncthreads();

        // ---- epilogue: this thread's (eb, ej) element ----
        {
            float zi = zbuf[eb * 16 + ej]      + zbuf[1024 + eb * 16 + ej]      + bi;
            float zf = zbuf[eb * 16 + 4 + ej]  + zbuf[1024 + eb * 16 + 4 + ej]  + bf;
            float zg = zbuf[eb * 16 + 8 + ej]  + zbuf[1024 + eb * 16 + 8 + ej]  + bg;
            float zo = zbuf[eb * 16 + 12 + ej] + zbuf[1024 + eb * 16 + 12 + ej] + bo;

            bool rs = ru8 ? (r8[t * BB + eb] != 0) : (r32[t * BB + eb] != 0);
            if (rs) c = 0.0f;   // h was pre-masked at write time

            float iv = sigf(zi);
            float fv = sigf(zf);
            float gv = tanhf(zg);
            float ov = sigf(zo);
            float ncr = fv * c + iv * gv;
            float nh = ov * tanhf(ncr);
            c = clampf1(ncr);
            float nhc = clampf1(nh);

            ys[(size_t)t * BB * HH + (size_t)eb * HH + jcol] = nhc;
            if (t + 1 < TT) {
                bool rs2 = ru8 ? (r8[(t + 1) * BB + eb] != 0) : (r32[(t + 1) * BB + eb] != 0);
                g_h[(t + 1) & 1][jcol * BB + eb] = rs2 ? 0.0f : nhc;
            }
        }

        // ---- grid-wide barrier ----
        if (tid == 0) {
            __threadfence();
            atomicAdd(&g_bar, 1u);
            unsigned target = (unsigned)(t + 1) * nblocks;
            while (*((volatile unsigned*)&g_bar) < target) { __nanosleep(32); }
            __threadfence();
        }
        __syncthreads();
    }
}

// ---------------- launch ----------------
extern "C" void kernel_launch(void* const* d_in, const int* in_sizes, int n_in,
                              void* d_out, int out_size) {
    const float* xs     = (const float*)d_in[0];
    const void*  resets = d_in[1];
    const float* c0     = (const float*)d_in[2];
    const float* h0     = (const float*)d_in[3];
    const float* Wi     = (const float*)d_in[4];
    const float* Wh     = (const float*)d_in[5];
    const float* bias   = (const float*)d_in[6];
    float* ys = (float*)d_out;

    cudaFuncSetAttribute(lstm_main, cudaFuncAttributeMaxDynamicSharedMemorySize, SMEM_BYTES);

    k_detect<<<1, 256>>>((const unsigned char*)resets);
    k_prep<<<TT, 256>>>(xs, h0, resets);
    lstm_main<<<128, 256, SMEM_BYTES>>>(Wi, Wh, bias, c0, resets, ys);
}

// round 4
// speedup vs baseline: 1.7239x; 1.7239x over previous
#include <cuda_runtime.h>
#include <cstdint>

#define TT 512
#define BB 64
#define HH 512

typedef unsigned long long ull;

// ---------------- device scratch (static: no runtime allocation) ----------------
__device__ float g_xT[(size_t)TT * HH * BB];   // [t][k][b]  (64 MB)
__device__ float g_h[2][HH * BB];              // double-buffered h, [buf][k*B + b]
__device__ unsigned g_bar;                     // grid barrier counter
__device__ int g_r_u8;                         // 1 if resets is 1-byte bool, 0 if int32

// ---------------- helpers ----------------
static __device__ __forceinline__ ull ffma2(ull a, ull b, ull c) {
    ull d;
    asm("fma.rn.f32x2 %0, %1, %2, %3;" : "=l"(d) : "l"(a), "l"(b), "l"(c));
    return d;
}
static __device__ __forceinline__ float lo32(ull v) { return __uint_as_float((unsigned)(v & 0xffffffffull)); }
static __device__ __forceinline__ float hi32(ull v) { return __uint_as_float((unsigned)(v >> 32)); }
static __device__ __forceinline__ ull ldg_pair(const float* p) {
    double v = __ldcg((const double*)p);
    return __double_as_longlong(v);
}
static __device__ __forceinline__ float sigf(float x) { return 1.0f / (1.0f + __expf(-x)); }
static __device__ __forceinline__ float clampf1(float x) { return fminf(fmaxf(x, -1.0f), 1.0f); }

// ---------------- kernel 0: reset-dtype detection + barrier reset ----------------
__global__ void k_detect(const unsigned char* __restrict__ r) {
    __shared__ int nz;
    if (threadIdx.x == 0) { nz = 0; g_bar = 0u; }
    __syncthreads();
    int loc = 0;
    for (int i = threadIdx.x; i < TT * BB; i += blockDim.x)
        if ((i & 3) && r[i]) loc = 1;
    if (loc) atomicOr(&nz, 1);
    __syncthreads();
    if (threadIdx.x == 0) g_r_u8 = nz;
}

// ---------------- kernel 1: transpose xs -> xT[t][k][b]; init h buffer ----------------
__global__ void k_prep(const float* __restrict__ xs, const float* __restrict__ h0,
                       const void* __restrict__ resets) {
    __shared__ float tile[64][65];
    const int t = blockIdx.x;
    for (int kt = 0; kt < 8; ++kt) {
        for (int idx = threadIdx.x; idx < 64 * 64; idx += blockDim.x) {
            int bb = idx >> 6, kk = idx & 63;
            tile[bb][kk] = xs[((size_t)t * BB + bb) * HH + kt * 64 + kk];
        }
        __syncthreads();
        for (int idx = threadIdx.x; idx < 64 * 64; idx += blockDim.x) {
            int kk = idx >> 6, bb = idx & 63;
            g_xT[(size_t)t * HH * BB + (size_t)(kt * 64 + kk) * BB + bb] = tile[bb][kk];
        }
        __syncthreads();
    }
    if (t == 0) {
        const int ru8 = g_r_u8;
        const unsigned char* r8 = (const unsigned char*)resets;
        const int* r32 = (const int*)resets;
        for (int idx = threadIdx.x; idx < HH * BB; idx += blockDim.x) {
            int b = idx & 63, k = idx >> 6;
            bool rs = ru8 ? (r8[b] != 0) : (r32[b] != 0);   // resets[0][b]
            g_h[0][idx] = rs ? 0.0f : h0[b * HH + k];
        }
    }
}

// ---------------- kernel 2: persistent scanned-LSTM ----------------
// 128 CTAs x 256 threads. CTA c owns state columns j in [4c, 4c+4) -> 16 z-cols.
// Thread identity (GEMM): ksplit = tid>>5 (64 k's each), bp = tid&31 (b pair 2bp, 2bp+1).
// Each thread accumulates ALL 16 local z-columns for its (k-range, b-pair) as f32x2
// pairs over b; weights broadcast from SMEM (warp-uniform address).
// SMEM: wdup (duplicated f32 pairs) [k=512][m=2][col=16] = 128KB
//       zbuf [ksplit=8][b=64][pad 17 floats] = 34816B
#define ZPAD 17
#define ZSPLIT (64 * ZPAD)           // floats per ksplit slab
#define SMEM_BYTES (131072 + 8 * ZSPLIT * 4)

__global__ __launch_bounds__(256, 1)
void lstm_main(const float* __restrict__ Wi, const float* __restrict__ Wh,
               const float* __restrict__ bias, const float* __restrict__ c0,
               const void* __restrict__ resets, float* __restrict__ ys) {
    extern __shared__ char smem[];
    float2* wdup = (float2*)smem;                    // [k][32] dup pairs
    float*  zbuf = (float*)(smem + 131072);          // [8][64][ZPAD]

    const int tid = threadIdx.x;
    const int cta = blockIdx.x;

    // ---- prologue: load this CTA's weight slice, duplicated into pairs ----
    for (int idx = tid; idx < 512 * 32; idx += 256) {
        int k = idx >> 5, r = idx & 31, m = r >> 4, l = r & 15;
        int g = l >> 2, j = l & 3;
        int col = g * 512 + cta * 4 + j;
        float w = (m ? Wh : Wi)[k * 2048 + col];
        wdup[idx] = make_float2(w, w);
    }

    // ---- per-thread epilogue identity: one (b, j) state element ----
    const int eb = tid >> 2;           // 0..63
    const int ej = tid & 3;            // 0..3
    const int jcol = cta * 4 + ej;     // global H index
    float c = c0[eb * HH + jcol];
    const float bi = bias[jcol];
    const float bf = bias[512 + jcol];
    const float bg = bias[1024 + jcol];
    const float bo = bias[1536 + jcol];
    const int ru8 = g_r_u8;
    const unsigned char* r8 = (const unsigned char*)resets;
    const int* r32 = (const int*)resets;

    // ---- GEMM identity ----
    const int ks = tid >> 5;           // 0..7
    const int bp = tid & 31;           // 0..31
    const int b0 = 2 * bp;
    const int kbeg = ks * 64;
    const ulonglong2* wbase = (const ulonglong2*)(wdup) + kbeg * 16;  // 16 u2 per k
    float* zme = zbuf + ks * ZSPLIT;

    __syncthreads();

    const unsigned nblocks = gridDim.x;

    for (int t = 0; t < TT; ++t) {
        const float* xk = g_xT + (size_t)t * (HH * BB) + kbeg * BB + b0;
        const float* hk = g_h[t & 1] + kbeg * BB + b0;

        ull acc[16];
        #pragma unroll
        for (int i = 0; i < 16; ++i) acc[i] = 0ull;

        ull xb[4], hb[4];
        #pragma unroll
        for (int u = 0; u < 4; ++u) {
            xb[u] = ldg_pair(xk + u * BB);
            hb[u] = ldg_pair(hk + u * BB);
        }

        #pragma unroll 1
        for (int kk = 0; kk < 60; kk += 4) {
            ull xn[4], hn[4];
            #pragma unroll
            for (int u = 0; u < 4; ++u) {
                xn[u] = ldg_pair(xk + (kk + 4 + u) * BB);
                hn[u] = ldg_pair(hk + (kk + 4 + u) * BB);
            }
            #pragma unroll
            for (int u = 0; u < 4; ++u) {
                const ulonglong2* w = wbase + (kk + u) * 16;
                #pragma unroll
                for (int c2 = 0; c2 < 8; ++c2) {
                    const ulonglong2 wi = w[c2];
                    const ulonglong2 wh = w[c2 + 8];
                    acc[2 * c2]     = ffma2(wi.x, xb[u], acc[2 * c2]);
                    acc[2 * c2]     = ffma2(wh.x, hb[u], acc[2 * c2]);
                    acc[2 * c2 + 1] = ffma2(wi.y, xb[u], acc[2 * c2 + 1]);
                    acc[2 * c2 + 1] = ffma2(wh.y, hb[u], acc[2 * c2 + 1]);
                }
            }
            #pragma unroll
            for (int u = 0; u < 4; ++u) { xb[u] = xn[u]; hb[u] = hn[u]; }
        }
        // final block (k = 60..63), no prefetch
        #pragma unroll
        for (int u = 0; u < 4; ++u) {
            const ulonglong2* w = wbase + (60 + u) * 16;
            #pragma unroll
            for (int c2 = 0; c2 < 8; ++c2) {
                const ulonglong2 wi = w[c2];
                const ulonglong2 wh = w[c2 + 8];
                acc[2 * c2]     = ffma2(wi.x, xb[u], acc[2 * c2]);
                acc[2 * c2]     = ffma2(wh.x, hb[u], acc[2 * c2]);
                acc[2 * c2 + 1] = ffma2(wi.y, xb[u], acc[2 * c2 + 1]);
                acc[2 * c2 + 1] = ffma2(wh.y, hb[u], acc[2 * c2 + 1]);
            }
        }

        // write z partials: zme[b][col], pad-17 rows (2-way conflict max)
        {
            float* z0 = zme + b0 * ZPAD;
            float* z1 = zme + (b0 + 1) * ZPAD;
            #pragma unroll
            for (int cc = 0; cc < 16; ++cc) {
                z0[cc] = lo32(acc[cc]);
                z1[cc] = hi32(acc[cc]);
            }
        }
        __syncthreads();

        // ---- epilogue: this thread's (eb, ej) element ----
        {
            float zi = bi, zf = bf, zg = bg, zo = bo;
            #pragma unroll
            for (int s = 0; s < 8; ++s) {
                const float* zr = zbuf + s * ZSPLIT + eb * ZPAD;
                zi += zr[ej];
                zf += zr[4 + ej];
                zg += zr[8 + ej];
                zo += zr[12 + ej];
            }

            bool rs = ru8 ? (r8[t * BB + eb] != 0) : (r32[t * BB + eb] != 0);
            if (rs) c = 0.0f;   // h was pre-masked at write time

            float iv = sigf(zi);
            float fv = sigf(zf);
            float gv = tanhf(zg);
            float ov = sigf(zo);
            float ncr = fv * c + iv * gv;
            float nh = ov * tanhf(ncr);
            c = clampf1(ncr);
            float nhc = clampf1(nh);

            ys[(size_t)t * BB * HH + (size_t)eb * HH + jcol] = nhc;
            if (t + 1 < TT) {
                bool rs2 = ru8 ? (r8[(t + 1) * BB + eb] != 0) : (r32[(t + 1) * BB + eb] != 0);
                g_h[(t + 1) & 1][jcol * BB + eb] = rs2 ? 0.0f : nhc;
            }
        }

        // ---- grid-wide barrier (all h-stores in this CTA complete first) ----
        __syncthreads();
        if (tid == 0) {
            __threadfence();
            atomicAdd(&g_bar, 1u);
            unsigned target = (unsigned)(t + 1) * nblocks;
            while (*((volatile unsigned*)&g_bar) < target) { __nanosleep(32); }
            __threadfence();
        }
        __syncthreads();
    }
}

// ---------------- launch ----------------
extern "C" void kernel_launch(void* const* d_in, const int* in_sizes, int n_in,
                              void* d_out, int out_size) {
    const float* xs     = (const float*)d_in[0];
    const void*  resets = d_in[1];
    const float* c0     = (const float*)d_in[2];
    const float* h0     = (const float*)d_in[3];
    const float* Wi     = (const float*)d_in[4];
    const float* Wh     = (const float*)d_in[5];
    const float* bias   = (const float*)d_in[6];
    float* ys = (float*)d_out;

    cudaFuncSetAttribute(lstm_main, cudaFuncAttributeMaxDynamicSharedMemorySize, SMEM_BYTES);

    k_detect<<<1, 256>>>((const unsigned char*)resets);
    k_prep<<<TT, 256>>>(xs, h0, resets);
    lstm_main<<<128, 256, SMEM_BYTES>>>(Wi, Wh, bias, c0, resets, ys);
}

// round 6
// speedup vs baseline: 2.2979x; 1.3329x over previous
#include <cuda_runtime.h>
#include <cuda_bf16.h>
#include <cstdint>

#define TT 512
#define BB 64
#define HH 512
#define MM (TT * BB)        // 32768
#define NN (4 * HH)         // 2048

typedef unsigned long long ull;

// ---------------- device scratch (static) ----------------
__device__ float g_zx[(size_t)MM * NN];             // 256 MB, [m][n] row-major
__device__ __nv_bfloat16 g_xhi[(size_t)MM * HH];    // 32 MB
__device__ __nv_bfloat16 g_xlo[(size_t)MM * HH];    // 32 MB
__device__ __nv_bfloat16 g_whi[(size_t)HH * NN];    // 2 MB
__device__ __nv_bfloat16 g_wlo[(size_t)HH * NN];    // 2 MB
__device__ float g_h[2][HH * BB];                   // [buf][k*B + b]
__device__ unsigned g_bar;
__device__ int g_r_u8;

// ---------------- helpers ----------------
static __device__ __forceinline__ ull ffma2(ull a, ull b, ull c) {
    ull d;
    asm("fma.rn.f32x2 %0, %1, %2, %3;" : "=l"(d) : "l"(a), "l"(b), "l"(c));
    return d;
}
static __device__ __forceinline__ float lo32(ull v) { return __uint_as_float((unsigned)(v & 0xffffffffull)); }
static __device__ __forceinline__ float hi32(ull v) { return __uint_as_float((unsigned)(v >> 32)); }
static __device__ __forceinline__ ull ldg_pair(const float* p) {
    double v = __ldcg((const double*)p);
    return __double_as_longlong(v);
}
static __device__ __forceinline__ float sigf(float x) { return 1.0f / (1.0f + __expf(-x)); }
static __device__ __forceinline__ float clampf1(float x) { return fminf(fmaxf(x, -1.0f), 1.0f); }

static __device__ __forceinline__ void cpa16(uint32_t dst, const void* src) {
    asm volatile("cp.async.cg.shared.global [%0],[%1],16;\n" :: "r"(dst), "l"(src));
}
#define LDSM4(R, addr) \
    asm volatile("ldmatrix.sync.aligned.m8n8.x4.shared.b16 {%0,%1,%2,%3},[%4];" \
        : "=r"((R)[0]), "=r"((R)[1]), "=r"((R)[2]), "=r"((R)[3]) : "r"(addr))
#define LDSM2T(R, addr) \
    asm volatile("ldmatrix.sync.aligned.m8n8.x2.trans.shared.b16 {%0,%1},[%2];" \
        : "=r"((R)[0]), "=r"((R)[1]) : "r"(addr))
#define MMA_BF16(C, A, B) \
    asm volatile("mma.sync.aligned.m16n8k16.row.col.f32.bf16.bf16.f32 " \
        "{%0,%1,%2,%3},{%4,%5,%6,%7},{%8,%9},{%0,%1,%2,%3};" \
        : "+f"((C)[0]), "+f"((C)[1]), "+f"((C)[2]), "+f"((C)[3]) \
        : "r"((A)[0]), "r"((A)[1]), "r"((A)[2]), "r"((A)[3]), "r"((B)[0]), "r"((B)[1]))

// ---------------- kernel: reset-dtype detection + barrier reset ----------------
__global__ void k_detect(const unsigned char* __restrict__ r) {
    __shared__ int nz;
    if (threadIdx.x == 0) { nz = 0; g_bar = 0u; }
    __syncthreads();
    int loc = 0;
    for (int i = threadIdx.x; i < TT * BB; i += blockDim.x)
        if ((i & 3) && r[i]) loc = 1;
    if (loc) atomicOr(&nz, 1);
    __syncthreads();
    if (threadIdx.x == 0) g_r_u8 = nz;
}

// ---------------- conversion kernels: fp32 -> bf16 hi/lo split ----------------
__global__ void k_convert_x(const float* __restrict__ xs) {
    size_t i0 = ((size_t)blockIdx.x * blockDim.x + threadIdx.x) * 4;
    #pragma unroll
    for (int u = 0; u < 4; ++u) {
        size_t i = i0 + u;
        if (i < (size_t)MM * HH) {
            float v = xs[i];
            __nv_bfloat16 hi = __float2bfloat16(v);
            g_xhi[i] = hi;
            g_xlo[i] = __float2bfloat16(v - __bfloat162float(hi));
        }
    }
}
__global__ void k_convert_w(const float* __restrict__ Wi) {
    size_t i0 = ((size_t)blockIdx.x * blockDim.x + threadIdx.x) * 4;
    #pragma unroll
    for (int u = 0; u < 4; ++u) {
        size_t i = i0 + u;
        if (i < (size_t)HH * NN) {
            float v = Wi[i];
            __nv_bfloat16 hi = __float2bfloat16(v);
            g_whi[i] = hi;
            g_wlo[i] = __float2bfloat16(v - __bfloat162float(hi));
        }
    }
}

// ---------------- kernel: h init ----------------
__global__ void k_hinit(const float* __restrict__ h0, const void* __restrict__ resets) {
    const int ru8 = g_r_u8;
    const unsigned char* r8 = (const unsigned char*)resets;
    const int* r32 = (const int*)resets;
    for (int idx = threadIdx.x; idx < HH * BB; idx += blockDim.x) {
        int b = idx & 63, k = idx >> 6;
        bool rs = ru8 ? (r8[b] != 0) : (r32[b] != 0);
        g_h[0][idx] = rs ? 0.0f : h0[b * HH + k];
    }
}

// ---------------- kernel: zx = x @ Wi  (bf16 3-split tensor-core GEMM) ----------------
// Tile: CTA 128(m) x 128(n), K=512 in 32 chunks of 16, double-buffered cp.async.
// 8 warps: warp (wm 0..1, wn 0..3) -> warp tile 64(m) x 32(n).
#define AROW 24    // bf16 per A smem row (48 B, conflict-free for ldmatrix)
#define BROW 136   // bf16 per B smem row (272 B, conflict-free for ldmatrix.trans)

#define LOAD_STAGE(buf, ks) do {                                                           \
    const int kb_ = (ks) * 16;                                                             \
    _Pragma("unroll")                                                                      \
    for (int j_ = 0; j_ < 4; ++j_) {                                                       \
        int id_ = tid + 256 * j_;                                                          \
        if (id_ < 512) {                                                                   \
            int plane_ = id_ >> 8; int r_ = id_ & 255; int row_ = r_ >> 1; int half_ = r_ & 1; \
            const __nv_bfloat16* src_ = (plane_ ? g_xlo : g_xhi)                           \
                + (size_t)(mbase + row_) * HH + kb_ + half_ * 8;                           \
            uint32_t dst_ = Abase + (((buf) * 2 + plane_) * 128 * AROW + row_ * AROW + half_ * 8) * 2; \
            cpa16(dst_, src_);                                                             \
        } else {                                                                           \
            int id2_ = id_ - 512; int plane_ = id2_ >> 8; int r_ = id2_ & 255;             \
            int krow_ = r_ >> 4; int seg_ = r_ & 15;                                       \
            const __nv_bfloat16* src_ = (plane_ ? g_wlo : g_whi)                           \
                + (size_t)(kb_ + krow_) * NN + nbase + seg_ * 8;                           \
            uint32_t dst_ = Bbase + (((buf) * 2 + plane_) * 16 * BROW + krow_ * BROW + seg_ * 8) * 2; \
            cpa16(dst_, src_);                                                             \
        }                                                                                  \
    } } while (0)

__global__ __launch_bounds__(256) void k_mm_pre() {
    __shared__ __align__(128) __nv_bfloat16 Asm[2][2][128 * AROW];
    __shared__ __align__(128) __nv_bfloat16 Bsm[2][2][16 * BROW];
    const int tid = threadIdx.x;
    const int nbase = blockIdx.x * 128;
    const int mbase = blockIdx.y * 128;
    const int wid = tid >> 5, lane = tid & 31;
    const int wm = wid & 1, wn = wid >> 1;

    uint32_t Abase = (uint32_t)__cvta_generic_to_shared(&Asm[0][0][0]);
    uint32_t Bbase = (uint32_t)__cvta_generic_to_shared(&Bsm[0][0][0]);

    const int gid = lane >> 2, tig = lane & 3;
    const int arow = (lane & 7) + 8 * ((lane >> 3) & 1);
    const int acol = (lane >> 4) * 8;
    const int bk = lane & 15;

    float c[4][4][4] = {};

    LOAD_STAGE(0, 0);
    asm volatile("cp.async.commit_group;\n");

    #pragma unroll 1
    for (int ks = 0; ks < 32; ++ks) {
        const int buf = ks & 1;
        if (ks < 31) {
            LOAD_STAGE((ks + 1) & 1, ks + 1);
            asm volatile("cp.async.commit_group;\n");
            asm volatile("cp.async.wait_group 1;\n");
        } else {
            asm volatile("cp.async.wait_group 0;\n");
        }
        __syncthreads();

        uint32_t a_hi[4][4], a_lo[4][4];
        #pragma unroll
        for (int mi = 0; mi < 4; ++mi) {
            int rowoff = wm * 64 + mi * 16 + arow;
            uint32_t ah = Abase + ((buf * 2 + 0) * 128 * AROW + rowoff * AROW + acol) * 2;
            uint32_t al = Abase + ((buf * 2 + 1) * 128 * AROW + rowoff * AROW + acol) * 2;
            LDSM4(a_hi[mi], ah);
            LDSM4(a_lo[mi], al);
        }
        uint32_t bhf[4][2], blf[4][2];
        #pragma unroll
        for (int ni = 0; ni < 4; ++ni) {
            int n0 = wn * 32 + ni * 8;
            uint32_t bh = Bbase + ((buf * 2 + 0) * 16 * BROW + bk * BROW + n0) * 2;
            uint32_t bl = Bbase + ((buf * 2 + 1) * 16 * BROW + bk * BROW + n0) * 2;
            LDSM2T(bhf[ni], bh);
            LDSM2T(blf[ni], bl);
        }
        #pragma unroll
        for (int mi = 0; mi < 4; ++mi)
            #pragma unroll
            for (int ni = 0; ni < 4; ++ni) {
                MMA_BF16(c[mi][ni], a_hi[mi], bhf[ni]);
                MMA_BF16(c[mi][ni], a_hi[mi], blf[ni]);
                MMA_BF16(c[mi][ni], a_lo[mi], bhf[ni]);
            }
        __syncthreads();
    }

    // epilogue: write fp32 C to g_zx [m][n]
    #pragma unroll
    for (int mi = 0; mi < 4; ++mi)
        #pragma unroll
        for (int ni = 0; ni < 4; ++ni) {
            int m0 = mbase + wm * 64 + mi * 16 + gid;
            int n = nbase + wn * 32 + ni * 8 + tig * 2;
            *(float2*)(g_zx + (size_t)m0 * NN + n) = make_float2(c[mi][ni][0], c[mi][ni][1]);
            *(float2*)(g_zx + (size_t)(m0 + 8) * NN + n) = make_float2(c[mi][ni][2], c[mi][ni][3]);
        }
}

// ---------------- kernel: persistent scanned-LSTM (h @ Wh only) ----------------
// 128 CTAs x 256 threads. CTA c owns state columns j in [4c, 4c+4) -> 16 z-cols.
// GEMM identity: ksplit = tid>>5 (64 k each), bp = tid&31 (b pair 2bp, 2bp+1).
// SMEM: wdup (Wh slice, duplicated f32 pairs) [k=512][16] = 64KB
//       zbuf [ksplit=8][b=64][pad 17] = 34816B
#define ZPAD 17
#define ZSPLIT (64 * ZPAD)
#define SMEM_BYTES (65536 + 8 * ZSPLIT * 4)

__global__ __launch_bounds__(256, 1)
void lstm_main(const float* __restrict__ Wh, const float* __restrict__ bias,
               const float* __restrict__ c0, const void* __restrict__ resets,
               float* __restrict__ ys) {
    extern __shared__ char smem[];
    float2* wdup = (float2*)smem;                    // [k][16] dup pairs (Wh only)
    float*  zbuf = (float*)(smem + 65536);           // [8][64][ZPAD]

    const int tid = threadIdx.x;
    const int cta = blockIdx.x;

    // prologue: Wh slice, duplicated into f32 pairs
    for (int idx = tid; idx < 512 * 16; idx += 256) {
        int k = idx >> 4, l = idx & 15;
        int g = l >> 2, j = l & 3;
        float w = Wh[k * 2048 + g * 512 + cta * 4 + j];
        wdup[idx] = make_float2(w, w);
    }

    // epilogue identity: one (b, j) state element
    const int eb = tid >> 2;
    const int ej = tid & 3;
    const int jcol = cta * 4 + ej;
    float c = c0[eb * HH + jcol];
    const float bi = bias[jcol];
    const float bf = bias[512 + jcol];
    const float bg = bias[1024 + jcol];
    const float bo = bias[1536 + jcol];
    const int ru8 = g_r_u8;
    const unsigned char* r8 = (const unsigned char*)resets;
    const int* r32 = (const int*)resets;

    // GEMM identity
    const int ks = tid >> 5;
    const int bp = tid & 31;
    const int b0 = 2 * bp;
    const int kbeg = ks * 64;
    const ulonglong2* wbase = (const ulonglong2*)(wdup) + kbeg * 8;  // 8 u2 per k
    float* zme = zbuf + ks * ZSPLIT;

    __syncthreads();

    const unsigned nblocks = gridDim.x;

    for (int t = 0; t < TT; ++t) {
        // prefetch zx for this thread's epilogue element (hide DRAM latency under GEMM)
        const float* zxr = g_zx + (size_t)(t * BB + eb) * NN + jcol;
        float z0 = __ldcg(zxr);
        float z1 = __ldcg(zxr + 512);
        float z2 = __ldcg(zxr + 1024);
        float z3 = __ldcg(zxr + 1536);

        const float* hk = g_h[t & 1] + kbeg * BB + b0;

        ull acc[16];
        #pragma unroll
        for (int i = 0; i < 16; ++i) acc[i] = 0ull;

        ull hb[4];
        #pragma unroll
        for (int u = 0; u < 4; ++u) hb[u] = ldg_pair(hk + u * BB);

        #pragma unroll 1
        for (int kk = 0; kk < 60; kk += 4) {
            ull hn[4];
            #pragma unroll
            for (int u = 0; u < 4; ++u) hn[u] = ldg_pair(hk + (kk + 4 + u) * BB);
            #pragma unroll
            for (int u = 0; u < 4; ++u) {
                const ulonglong2* w = wbase + (kk + u) * 8;
                #pragma unroll
                for (int c2 = 0; c2 < 8; ++c2) {
                    const ulonglong2 wh = w[c2];
                    acc[2 * c2]     = ffma2(wh.x, hb[u], acc[2 * c2]);
                    acc[2 * c2 + 1] = ffma2(wh.y, hb[u], acc[2 * c2 + 1]);
                }
            }
            #pragma unroll
            for (int u = 0; u < 4; ++u) hb[u] = hn[u];
        }
        #pragma unroll
        for (int u = 0; u < 4; ++u) {
            const ulonglong2* w = wbase + (60 + u) * 8;
            #pragma unroll
            for (int c2 = 0; c2 < 8; ++c2) {
                const ulonglong2 wh = w[c2];
                acc[2 * c2]     = ffma2(wh.x, hb[u], acc[2 * c2]);
                acc[2 * c2 + 1] = ffma2(wh.y, hb[u], acc[2 * c2 + 1]);
            }
        }

        {
            float* zz0 = zme + b0 * ZPAD;
            float* zz1 = zme + (b0 + 1) * ZPAD;
            #pragma unroll
            for (int cc = 0; cc < 16; ++cc) {
                zz0[cc] = lo32(acc[cc]);
                zz1[cc] = hi32(acc[cc]);
            }
        }
        __syncthreads();

        // epilogue
        {
            float zi = z0 + bi, zf = z1 + bf, zg = z2 + bg, zo = z3 + bo;
            #pragma unroll
            for (int s = 0; s < 8; ++s) {
                const float* zr = zbuf + s * ZSPLIT + eb * ZPAD;
                zi += zr[ej];
                zf += zr[4 + ej];
                zg += zr[8 + ej];
                zo += zr[12 + ej];
            }

            bool rs = ru8 ? (r8[t * BB + eb] != 0) : (r32[t * BB + eb] != 0);
            if (rs) c = 0.0f;

            float iv = sigf(zi);
            float fv = sigf(zf);
            float gv = tanhf(zg);
            float ov = sigf(zo);
            float ncr = fv * c + iv * gv;
            float nh = ov * tanhf(ncr);
            c = clampf1(ncr);
            float nhc = clampf1(nh);

            ys[(size_t)t * BB * HH + (size_t)eb * HH + jcol] = nhc;
            if (t + 1 < TT) {
                bool rs2 = ru8 ? (r8[(t + 1) * BB + eb] != 0) : (r32[(t + 1) * BB + eb] != 0);
                g_h[(t + 1) & 1][jcol * BB + eb] = rs2 ? 0.0f : nhc;
            }
        }

        __syncthreads();
        if (tid == 0) {
            __threadfence();
            atomicAdd(&g_bar, 1u);
            unsigned target = (unsigned)(t + 1) * nblocks;
            while (*((volatile unsigned*)&g_bar) < target) { __nanosleep(32); }
            __threadfence();
        }
        __syncthreads();
    }
}

// ---------------- launch ----------------
extern "C" void kernel_launch(void* const* d_in, const int* in_sizes, int n_in,
                              void* d_out, int out_size) {
    const float* xs     = (const float*)d_in[0];
    const void*  resets = d_in[1];
    const float* c0     = (const float*)d_in[2];
    const float* h0     = (const float*)d_in[3];
    const float* Wi     = (const float*)d_in[4];
    const float* Wh     = (const float*)d_in[5];
    const float* bias   = (const float*)d_in[6];
    float* ys = (float*)d_out;

    cudaFuncSetAttribute(lstm_main, cudaFuncAttributeMaxDynamicSharedMemorySize, SMEM_BYTES);

    k_detect<<<1, 256>>>((const unsigned char*)resets);
    k_convert_x<<<16384, 256>>>(xs);
    k_convert_w<<<1024, 256>>>(Wi);
    k_hinit<<<1, 256>>>(h0, resets);
    dim3 gpre(16, 256);
    k_mm_pre<<<gpre, 256>>>();
    lstm_main<<<128, 256, SMEM_BYTES>>>(Wh, bias, c0, resets, ys);
}

// round 7
// speedup vs baseline: 2.4418x; 1.0626x over previous
#include <cuda_runtime.h>
#include <cuda_bf16.h>
#include <cstdint>

#define TT 512
#define BB 64
#define HH 512
#define MM (TT * BB)        // 32768
#define NN (4 * HH)         // 2048

typedef unsigned long long ull;

// ---------------- device scratch (static) ----------------
__device__ float g_zx[(size_t)MM * NN];             // 256 MB, [m][n]
__device__ __nv_bfloat16 g_xhi[(size_t)MM * HH];    // 32 MB
__device__ __nv_bfloat16 g_xlo[(size_t)MM * HH];    // 32 MB
__device__ __nv_bfloat16 g_whi[(size_t)HH * NN];    // 2 MB
__device__ __nv_bfloat16 g_wlo[(size_t)HH * NN];    // 2 MB
__device__ __nv_bfloat16 g_hb[2][2][BB * HH];       // h as bf16 planes [buf][hi/lo][b][k]
__device__ unsigned g_bar;
__device__ int g_r_u8;

// ---------------- helpers ----------------
static __device__ __forceinline__ float sigf(float x) { return 1.0f / (1.0f + __expf(-x)); }
static __device__ __forceinline__ float clampf1(float x) { return fminf(fmaxf(x, -1.0f), 1.0f); }
static __device__ __forceinline__ unsigned packbf(float a, float b) {
    __nv_bfloat162 t = __floats2bfloat162_rn(a, b);
    return *(unsigned*)&t;
}

static __device__ __forceinline__ void cpa16(uint32_t dst, const void* src) {
    asm volatile("cp.async.cg.shared.global [%0],[%1],16;\n" :: "r"(dst), "l"(src));
}
#define LDSM4(R, addr) \
    asm volatile("ldmatrix.sync.aligned.m8n8.x4.shared.b16 {%0,%1,%2,%3},[%4];" \
        : "=r"((R)[0]), "=r"((R)[1]), "=r"((R)[2]), "=r"((R)[3]) : "r"(addr))
#define LDSM2T(R, addr) \
    asm volatile("ldmatrix.sync.aligned.m8n8.x2.trans.shared.b16 {%0,%1},[%2];" \
        : "=r"((R)[0]), "=r"((R)[1]) : "r"(addr))
#define MMA_BF16(C, A, B) \
    asm volatile("mma.sync.aligned.m16n8k16.row.col.f32.bf16.bf16.f32 " \
        "{%0,%1,%2,%3},{%4,%5,%6,%7},{%8,%9},{%0,%1,%2,%3};" \
        : "+f"((C)[0]), "+f"((C)[1]), "+f"((C)[2]), "+f"((C)[3]) \
        : "r"((A)[0]), "r"((A)[1]), "r"((A)[2]), "r"((A)[3]), "r"((B)[0]), "r"((B)[1]))

// ---------------- kernel: reset-dtype detection + barrier reset ----------------
__global__ void k_detect(const unsigned char* __restrict__ r) {
    __shared__ int nz;
    if (threadIdx.x == 0) { nz = 0; g_bar = 0u; }
    __syncthreads();
    int loc = 0;
    for (int i = threadIdx.x; i < TT * BB; i += blockDim.x)
        if ((i & 3) && r[i]) loc = 1;
    if (loc) atomicOr(&nz, 1);
    __syncthreads();
    if (threadIdx.x == 0) g_r_u8 = nz;
}

// ---------------- conversion kernels ----------------
__global__ void k_convert_x(const float* __restrict__ xs) {
    size_t i0 = ((size_t)blockIdx.x * blockDim.x + threadIdx.x) * 4;
    #pragma unroll
    for (int u = 0; u < 4; ++u) {
        size_t i = i0 + u;
        if (i < (size_t)MM * HH) {
            float v = xs[i];
            __nv_bfloat16 hi = __float2bfloat16(v);
            g_xhi[i] = hi;
            g_xlo[i] = __float2bfloat16(v - __bfloat162float(hi));
        }
    }
}
__global__ void k_convert_w(const float* __restrict__ Wi) {
    size_t i0 = ((size_t)blockIdx.x * blockDim.x + threadIdx.x) * 4;
    #pragma unroll
    for (int u = 0; u < 4; ++u) {
        size_t i = i0 + u;
        if (i < (size_t)HH * NN) {
            float v = Wi[i];
            __nv_bfloat16 hi = __float2bfloat16(v);
            g_whi[i] = hi;
            g_wlo[i] = __float2bfloat16(v - __bfloat162float(hi));
        }
    }
}

// ---------------- kernel: h init (bf16 hi/lo planes, [b][k]) ----------------
__global__ void k_hinit(const float* __restrict__ h0, const void* __restrict__ resets) {
    const int ru8 = g_r_u8;
    const unsigned char* r8 = (const unsigned char*)resets;
    const int* r32 = (const int*)resets;
    for (int idx = threadIdx.x + blockIdx.x * blockDim.x; idx < HH * BB;
         idx += blockDim.x * gridDim.x) {
        int b = idx >> 9, k = idx & 511;
        bool rs = ru8 ? (r8[b] != 0) : (r32[b] != 0);
        float hv = rs ? 0.0f : h0[b * HH + k];
        __nv_bfloat16 hi = __float2bfloat16(hv);
        g_hb[0][0][idx] = hi;
        g_hb[0][1][idx] = __float2bfloat16(hv - __bfloat162float(hi));
    }
}

// ---------------- kernel: zx = x @ Wi  (bf16 3-split tensor-core GEMM) ----------------
#define AROW 24
#define BROW 136

#define LOAD_STAGE(buf, ks) do {                                                           \
    const int kb_ = (ks) * 16;                                                             \
    _Pragma("unroll")                                                                      \
    for (int j_ = 0; j_ < 4; ++j_) {                                                       \
        int id_ = tid + 256 * j_;                                                          \
        if (id_ < 512) {                                                                   \
            int plane_ = id_ >> 8; int r_ = id_ & 255; int row_ = r_ >> 1; int half_ = r_ & 1; \
            const __nv_bfloat16* src_ = (plane_ ? g_xlo : g_xhi)                           \
                + (size_t)(mbase + row_) * HH + kb_ + half_ * 8;                           \
            uint32_t dst_ = Abase + (((buf) * 2 + plane_) * 128 * AROW + row_ * AROW + half_ * 8) * 2; \
            cpa16(dst_, src_);                                                             \
        } else {                                                                           \
            int id2_ = id_ - 512; int plane_ = id2_ >> 8; int r_ = id2_ & 255;             \
            int krow_ = r_ >> 4; int seg_ = r_ & 15;                                       \
            const __nv_bfloat16* src_ = (plane_ ? g_wlo : g_whi)                           \
                + (size_t)(kb_ + krow_) * NN + nbase + seg_ * 8;                           \
            uint32_t dst_ = Bbase + (((buf) * 2 + plane_) * 16 * BROW + krow_ * BROW + seg_ * 8) * 2; \
            cpa16(dst_, src_);                                                             \
        }                                                                                  \
    } } while (0)

__global__ __launch_bounds__(256) void k_mm_pre() {
    __shared__ __align__(128) __nv_bfloat16 Asm[2][2][128 * AROW];
    __shared__ __align__(128) __nv_bfloat16 Bsm[2][2][16 * BROW];
    const int tid = threadIdx.x;
    const int nbase = blockIdx.x * 128;
    const int mbase = blockIdx.y * 128;
    const int wid = tid >> 5, lane = tid & 31;
    const int wm = wid & 1, wn = wid >> 1;

    uint32_t Abase = (uint32_t)__cvta_generic_to_shared(&Asm[0][0][0]);
    uint32_t Bbase = (uint32_t)__cvta_generic_to_shared(&Bsm[0][0][0]);

    const int gid = lane >> 2, tig = lane & 3;
    const int arow = (lane & 7) + 8 * ((lane >> 3) & 1);
    const int acol = (lane >> 4) * 8;
    const int bk = lane & 15;

    float c[4][4][4] = {};

    LOAD_STAGE(0, 0);
    asm volatile("cp.async.commit_group;\n");

    #pragma unroll 1
    for (int ks = 0; ks < 32; ++ks) {
        const int buf = ks & 1;
        if (ks < 31) {
            LOAD_STAGE((ks + 1) & 1, ks + 1);
            asm volatile("cp.async.commit_group;\n");
            asm volatile("cp.async.wait_group 1;\n");
        } else {
            asm volatile("cp.async.wait_group 0;\n");
        }
        __syncthreads();

        uint32_t a_hi[4][4], a_lo[4][4];
        #pragma unroll
        for (int mi = 0; mi < 4; ++mi) {
            int rowoff = wm * 64 + mi * 16 + arow;
            uint32_t ah = Abase + ((buf * 2 + 0) * 128 * AROW + rowoff * AROW + acol) * 2;
            uint32_t al = Abase + ((buf * 2 + 1) * 128 * AROW + rowoff * AROW + acol) * 2;
            LDSM4(a_hi[mi], ah);
            LDSM4(a_lo[mi], al);
        }
        uint32_t bhf[4][2], blf[4][2];
        #pragma unroll
        for (int ni = 0; ni < 4; ++ni) {
            int n0 = wn * 32 + ni * 8;
            uint32_t bh = Bbase + ((buf * 2 + 0) * 16 * BROW + bk * BROW + n0) * 2;
            uint32_t bl = Bbase + ((buf * 2 + 1) * 16 * BROW + bk * BROW + n0) * 2;
            LDSM2T(bhf[ni], bh);
            LDSM2T(blf[ni], bl);
        }
        #pragma unroll
        for (int mi = 0; mi < 4; ++mi)
            #pragma unroll
            for (int ni = 0; ni < 4; ++ni) {
                MMA_BF16(c[mi][ni], a_hi[mi], bhf[ni]);
                MMA_BF16(c[mi][ni], a_hi[mi], blf[ni]);
                MMA_BF16(c[mi][ni], a_lo[mi], bhf[ni]);
            }
        __syncthreads();
    }

    #pragma unroll
    for (int mi = 0; mi < 4; ++mi)
        #pragma unroll
        for (int ni = 0; ni < 4; ++ni) {
            int m0 = mbase + wm * 64 + mi * 16 + gid;
            int n = nbase + wn * 32 + ni * 8 + tig * 2;
            *(float2*)(g_zx + (size_t)m0 * NN + n) = make_float2(c[mi][ni][0], c[mi][ni][1]);
            *(float2*)(g_zx + (size_t)(m0 + 8) * NN + n) = make_float2(c[mi][ni][2], c[mi][ni][3]);
        }
}

// ---------------- kernel: persistent scanned-LSTM (tensor-core h @ Wh) ----------------
// 128 CTAs x 256 threads. CTA owns 16 z-cols: col(l) = (l>>2)*512 + cta*4 + (l&3).
// Warps K-split: warp w owns k in [64w, 64w+64). B (Wh) fragments live in registers.
// A (h) fragments loaded straight from global bf16 planes with ldcg.
#define ZP 18

__global__ __launch_bounds__(256, 1)
void lstm_main(const float* __restrict__ Wh, const float* __restrict__ bias,
               const float* __restrict__ c0, const void* __restrict__ resets,
               float* __restrict__ ys) {
    __shared__ float zs[8][64][ZP];   // 36,864 B

    const int tid = threadIdx.x;
    const int cta = blockIdx.x;
    const int wid = tid >> 5, lane = tid & 31;
    const int gid = lane >> 2, tig = lane & 3;
    const int wk = wid * 64;

    // ---- build register-resident B fragments from fp32 Wh (once) ----
    unsigned bh[2][4][2], bl[2][4][2];
    #pragma unroll
    for (int nt = 0; nt < 2; ++nt) {
        const int l = nt * 8 + gid;
        const int gcol = (l >> 2) * 512 + cta * 4 + (l & 3);
        #pragma unroll
        for (int kt = 0; kt < 4; ++kt) {
            const int k0 = wk + kt * 16 + 2 * tig;
            float f0 = Wh[(size_t)k0 * NN + gcol];
            float f1 = Wh[(size_t)(k0 + 1) * NN + gcol];
            float f2 = Wh[(size_t)(k0 + 8) * NN + gcol];
            float f3 = Wh[(size_t)(k0 + 9) * NN + gcol];
            float h0f = __bfloat162float(__float2bfloat16(f0));
            float h1f = __bfloat162float(__float2bfloat16(f1));
            float h2f = __bfloat162float(__float2bfloat16(f2));
            float h3f = __bfloat162float(__float2bfloat16(f3));
            bh[nt][kt][0] = packbf(h0f, h1f);
            bh[nt][kt][1] = packbf(h2f, h3f);
            bl[nt][kt][0] = packbf(f0 - h0f, f1 - h1f);
            bl[nt][kt][1] = packbf(f2 - h2f, f3 - h3f);
        }
    }

    // ---- epilogue identity: one (b, j) element ----
    const int eb = tid >> 2;
    const int ej = tid & 3;
    const int jcol = cta * 4 + ej;
    float c = c0[eb * HH + jcol];
    const float bi = bias[jcol];
    const float bf = bias[512 + jcol];
    const float bg = bias[1024 + jcol];
    const float bo = bias[1536 + jcol];
    const int ru8 = g_r_u8;
    const unsigned char* r8 = (const unsigned char*)resets;
    const int* r32 = (const int*)resets;

    const unsigned nblocks = gridDim.x;

    for (int t = 0; t < TT; ++t) {
        // zx prefetch for the epilogue element (hide DRAM latency under MMAs)
        const float* zxr = g_zx + (size_t)(t * BB + eb) * NN + jcol;
        float z0 = __ldcg(zxr);
        float z1 = __ldcg(zxr + 512);
        float z2 = __ldcg(zxr + 1024);
        float z3 = __ldcg(zxr + 1536);

        const __nv_bfloat16* hhi = g_hb[t & 1][0];
        const __nv_bfloat16* hlo = g_hb[t & 1][1];

        float acc[4][2][4];
        #pragma unroll
        for (int mt = 0; mt < 4; ++mt)
            #pragma unroll
            for (int nt = 0; nt < 2; ++nt)
                #pragma unroll
                for (int q = 0; q < 4; ++q) acc[mt][nt][q] = 0.0f;

        #pragma unroll
        for (int kt = 0; kt < 4; ++kt) {
            unsigned ahi[4][4], alo[4][4];
            #pragma unroll
            for (int mt = 0; mt < 4; ++mt) {
                const int r0 = mt * 16 + gid;
                const int k0 = wk + kt * 16 + 2 * tig;
                const unsigned* ph  = (const unsigned*)(hhi + r0 * HH + k0);
                const unsigned* ph8 = (const unsigned*)(hhi + (r0 + 8) * HH + k0);
                const unsigned* pl  = (const unsigned*)(hlo + r0 * HH + k0);
                const unsigned* pl8 = (const unsigned*)(hlo + (r0 + 8) * HH + k0);
                ahi[mt][0] = __ldcg(ph);
                ahi[mt][1] = __ldcg(ph8);
                ahi[mt][2] = __ldcg(ph + 4);
                ahi[mt][3] = __ldcg(ph8 + 4);
                alo[mt][0] = __ldcg(pl);
                alo[mt][1] = __ldcg(pl8);
                alo[mt][2] = __ldcg(pl + 4);
                alo[mt][3] = __ldcg(pl8 + 4);
            }
            #pragma unroll
            for (int mt = 0; mt < 4; ++mt)
                #pragma unroll
                for (int nt = 0; nt < 2; ++nt) {
                    MMA_BF16(acc[mt][nt], ahi[mt], bh[nt][kt]);
                    MMA_BF16(acc[mt][nt], ahi[mt], bl[nt][kt]);
                    MMA_BF16(acc[mt][nt], alo[mt], bh[nt][kt]);
                }
        }

        // write K-split partials
        #pragma unroll
        for (int mt = 0; mt < 4; ++mt)
            #pragma unroll
            for (int nt = 0; nt < 2; ++nt) {
                const int r0 = mt * 16 + gid;
                const int col = nt * 8 + 2 * tig;
                *(float2*)&zs[wid][r0][col]     = make_float2(acc[mt][nt][0], acc[mt][nt][1]);
                *(float2*)&zs[wid][r0 + 8][col] = make_float2(acc[mt][nt][2], acc[mt][nt][3]);
            }
        __syncthreads();

        // ---- epilogue ----
        {
            float zi = z0 + bi, zf = z1 + bf, zg = z2 + bg, zo = z3 + bo;
            #pragma unroll
            for (int s = 0; s < 8; ++s) {
                const float* zr = zs[s][eb];
                zi += zr[ej];
                zf += zr[4 + ej];
                zg += zr[8 + ej];
                zo += zr[12 + ej];
            }

            bool rs = ru8 ? (r8[t * BB + eb] != 0) : (r32[t * BB + eb] != 0);
            if (rs) c = 0.0f;

            float iv = sigf(zi);
            float fv = sigf(zf);
            float gv = tanhf(zg);
            float ov = sigf(zo);
            float ncr = fv * c + iv * gv;
            float nh = ov * tanhf(ncr);
            c = clampf1(ncr);
            float nhc = clampf1(nh);

            ys[(size_t)t * BB * HH + (size_t)eb * HH + jcol] = nhc;
            if (t + 1 < TT) {
                bool rs2 = ru8 ? (r8[(t + 1) * BB + eb] != 0) : (r32[(t + 1) * BB + eb] != 0);
                float hv = rs2 ? 0.0f : nhc;
                __nv_bfloat16 hi = __float2bfloat16(hv);
                const int nb = (t + 1) & 1;
                g_hb[nb][0][eb * HH + jcol] = hi;
                g_hb[nb][1][eb * HH + jcol] = __float2bfloat16(hv - __bfloat162float(hi));
            }
        }

        // ---- grid-wide barrier ----
        __syncthreads();
        if (tid == 0) {
            __threadfence();
            atomicAdd(&g_bar, 1u);
            unsigned target = (unsigned)(t + 1) * nblocks;
            while (*((volatile unsigned*)&g_bar) < target) { __nanosleep(32); }
            __threadfence();
        }
        __syncthreads();
    }
}

// ---------------- launch ----------------
extern "C" void kernel_launch(void* const* d_in, const int* in_sizes, int n_in,
                              void* d_out, int out_size) {
    const float* xs     = (const float*)d_in[0];
    const void*  resets = d_in[1];
    const float* c0     = (const float*)d_in[2];
    const float* h0     = (const float*)d_in[3];
    const float* Wi     = (const float*)d_in[4];
    const float* Wh     = (const float*)d_in[5];
    const float* bias   = (const float*)d_in[6];
    float* ys = (float*)d_out;

    k_detect<<<1, 256>>>((const unsigned char*)resets);
    k_convert_x<<<16384, 256>>>(xs);
    k_convert_w<<<1024, 256>>>(Wi);
    k_hinit<<<32, 256>>>(h0, resets);
    dim3 gpre(16, 256);
    k_mm_pre<<<gpre, 256>>>();
    lstm_main<<<128, 256>>>(Wh, bias, c0, resets, ys);
}